// round 12
// baseline (speedup 1.0000x reference)
#include <cuda_runtime.h>

// AddDecomposedRelativePositions, fixed bench shapes:
// B=8, q_h=q_w=k_h=k_w=64, C=64, L=127 (rel idx = i-j+63)
//
// Kernel A: 2*B*64 CTAs, each a non-redundant 64x64x64 GEMM.
//   A operand stored DUPLICATED in smem so LDS.128 yields pre-packed (a,a)
//   f32x2 operands; B pairs come pre-packed from smem too. Mainloop is
//   3x LDS.128 + 8x fma.rn.f32x2 per c — zero packing MOVs, fma-pipe bound.
// Kernel B: stream kernel — one CTA per 2 rows (2048 float4), 8 front-
//   batched LDG.128/thread (MLP_p1=8), rel rows staged in 1KB smem,
//   LDG/STG evict-first.

#define THREADS 256
#define PADB 68
#define PADA 136    // duplicated A row: 64 values stored twice, padded

__device__ float g_relh[8 * 64 * 64 * 64];   // [bx][w][kh]
__device__ float g_relw[8 * 64 * 64 * 64];   // [bx][w][kw]

__device__ __forceinline__ void fma2(unsigned long long& d,
                                     unsigned long long a,
                                     unsigned long long b) {
    asm("fma.rn.f32x2 %0, %1, %2, %0;" : "+l"(d) : "l"(a), "l"(b));
}
__device__ __forceinline__ float2 unpack2(unsigned long long v) {
    float2 f;
    asm("mov.b64 {%0, %1}, %2;" : "=f"(f.x), "=f"(f.y) : "l"(v));
    return f;
}

__global__ __launch_bounds__(THREADS, 4)
void relpos_gemm_kernel(const float* __restrict__ q,
                        const float* __restrict__ rph,
                        const float* __restrict__ rpw,
                        int nH)
{
    extern __shared__ float smem[];
    float* At2 = smem;                // At2[c*PADA + 2r] = At2[..+2r+1] = a
    float* Bt  = smem + 64 * PADA;    // Bt[c*PADB + k]

    const int t   = threadIdx.x;
    const int bid = blockIdx.x;
    const bool isH = (bid < nH);

    float* outBase;
    size_t rowStride;

    if (isH) {
        const int bx = bid;                 // b*64 + h
        const int h  = bx & 63;
        const float* qs = q + (size_t)bx * 4096;
        #pragma unroll 4
        for (int idx = t; idx < 4096; idx += THREADS) {
            int c = idx & 63, w = idx >> 6;
            float v = __ldg(&qs[idx]);                    // r = w
            *(float2*)&At2[c * PADA + 2 * w] = make_float2(v, v);
        }
        #pragma unroll 4
        for (int idx = t; idx < 4096; idx += THREADS) {
            int c = idx & 63, kh = idx >> 6;
            Bt[c * PADB + kh] = __ldg(&rph[(h + 63 - kh) * 64 + c]);
        }
        outBase   = g_relh + (size_t)bx * 4096;           // [w][kh]
        rowStride = 64;
    } else {
        const int i2 = bid - nH;            // b*64 + w
        const int b  = i2 >> 6;
        const int w  = i2 & 63;
        #pragma unroll 4
        for (int idx = t; idx < 4096; idx += THREADS) {
            int c = idx & 63, h = idx >> 6;
            float v = __ldg(&q[((size_t)(b * 4096 + h * 64 + w) << 6) + c]);
            *(float2*)&At2[c * PADA + 2 * h] = make_float2(v, v);   // r = h
        }
        #pragma unroll 4
        for (int idx = t; idx < 4096; idx += THREADS) {
            int c = idx & 63, kw = idx >> 6;
            Bt[c * PADB + kw] = __ldg(&rpw[(w + 63 - kw) * 64 + c]);
        }
        outBase   = g_relw + ((size_t)(b * 4096 + w) << 6);  // row h stride 4096
        rowStride = 4096;
    }
    __syncthreads();

    const int rb = t >> 4;            // output rows 4rb..4rb+3
    const int kb = t & 15;            // output cols 4kb..4kb+3

    unsigned long long acc[4][2];
    #pragma unroll
    for (int j = 0; j < 4; ++j) { acc[j][0] = 0ull; acc[j][1] = 0ull; }

    #pragma unroll 4
    for (int c = 0; c < 64; ++c) {
        // pre-packed (a,a) pairs straight from duplicated smem
        ulonglong2 aP0 = *(const ulonglong2*)&At2[c * PADA + 8 * rb];     // (a0,a0),(a1,a1)
        ulonglong2 aP1 = *(const ulonglong2*)&At2[c * PADA + 8 * rb + 4]; // (a2,a2),(a3,a3)
        ulonglong2 bv  = *(const ulonglong2*)&Bt [c * PADB + 4 * kb];     // (b0,b1),(b2,b3)
        fma2(acc[0][0], aP0.x, bv.x);  fma2(acc[0][1], aP0.x, bv.y);
        fma2(acc[1][0], aP0.y, bv.x);  fma2(acc[1][1], aP0.y, bv.y);
        fma2(acc[2][0], aP1.x, bv.x);  fma2(acc[2][1], aP1.x, bv.y);
        fma2(acc[3][0], aP1.y, bv.x);  fma2(acc[3][1], aP1.y, bv.y);
    }

    #pragma unroll
    for (int j = 0; j < 4; ++j) {
        float2 lo = unpack2(acc[j][0]);
        float2 hi = unpack2(acc[j][1]);
        *(float4*)&outBase[(size_t)(4 * rb + j) * rowStride + 4 * kb] =
            make_float4(lo.x, lo.y, hi.x, hi.y);
    }
}

// ---- Kernel B: one CTA per 2 rows; 2048 contiguous float4 each ----
__global__ __launch_bounds__(THREADS)
void stream_add_kernel(const float4* __restrict__ a4,
                       float4* __restrict__ o4)
{
    __shared__ float  rhs[128];    // rel_h rows w0,w0+1 (64 floats each)
    __shared__ float4 rw4s[32];    // rel_w rows w0,w0+1 (16 float4 each)

    const int t   = threadIdx.x;
    const int cta = blockIdx.x;               // row pair index

    const float4* ap = a4 + (size_t)cta * 2048;
    float4*       op = o4 + (size_t)cta * 2048;

    // 8 front-batched streaming loads (MLP_p1 = 8)
    float4 a[8];
    #pragma unroll
    for (int k = 0; k < 8; ++k)
        a[k] = __ldcs(&ap[t + 256 * k]);

    if (t < 32)
        ((float4*)rhs)[t] = __ldg(&((const float4*)g_relh)[cta * 32 + t]);
    else if (t >= 64 && t < 96)
        rw4s[t - 64] = __ldg(&((const float4*)g_relw)[cta * 32 + (t - 64)]);
    __syncthreads();

    #pragma unroll
    for (int k = 0; k < 8; ++k) {
        int idx = t + 256 * k;
        int wl  = idx >> 10;       // 0..1 (row within pair)
        int kh  = (idx >> 4) & 63;
        int kw4 = idx & 15;
        float  rh = rhs[wl * 64 + kh];
        float4 rw = rw4s[wl * 16 + kw4];
        float4 v  = a[k];
        v.x += rh + rw.x;
        v.y += rh + rw.y;
        v.z += rh + rw.z;
        v.w += rh + rw.w;
        __stcs(&op[idx], v);
    }
}

extern "C" void kernel_launch(void* const* d_in, const int* in_sizes, int n_in,
                              void* d_out, int out_size)
{
    const float* attn = (const float*)d_in[0];
    const float* q    = (const float*)d_in[1];
    const float* rph  = (const float*)d_in[2];
    const float* rpw  = (const float*)d_in[3];
    float* out = (float*)d_out;

    const int B  = in_sizes[0] / (4096 * 4096);   // 8 on the bench
    const int nH = B * 64;
    const int smem_bytes = (64 * PADA + 64 * PADB) * sizeof(float);  // 52224

    cudaFuncSetAttribute(relpos_gemm_kernel,
                         cudaFuncAttributeMaxDynamicSharedMemorySize,
                         smem_bytes);

    relpos_gemm_kernel<<<2 * nH, THREADS, smem_bytes>>>(q, rph, rpw, nH);

    stream_add_kernel<<<B * 64 * 64 / 2, THREADS>>>(
        (const float4*)attn, (float4*)out);
}